// round 5
// baseline (speedup 1.0000x reference)
#include <cuda_runtime.h>
#include <cuda_bf16.h>

#define NN 50000
#define EE 800000
#define RR 8
#define HH 128

typedef unsigned long long ull;

// ---------------- scratch (device globals; no allocation allowed) ----------------
__device__ float    g_xw[(size_t)RR * NN * HH];   // per-relation transformed features
__device__ float    g_sq[RR * NN];
__device__ float    g_sk[RR * NN];
__device__ float    g_alpha[EE];
__device__ unsigned g_menc[NN];
__device__ float    g_h1[(size_t)NN * HH];
__device__ float    g_h2[(size_t)NN * HH];
__device__ int      g_counts[NN];
__device__ int      g_off[NN + 1];
__device__ int      g_cursor[NN];
__device__ int      g_sorted[EE];
__device__ float    g_wlt[HH * HH];

// ---------------- helpers ----------------
__device__ __forceinline__ unsigned fenc(float f) {
    unsigned u = __float_as_uint(f);
    return (u & 0x80000000u) ? ~u : (u | 0x80000000u);
}
__device__ __forceinline__ float fdec(unsigned u) {
    unsigned b = (u & 0x80000000u) ? (u ^ 0x80000000u) : ~u;
    return __uint_as_float(b);
}

#define FMA2(d, a, b, c) \
    asm("fma.rn.f32x2 %0, %1, %2, %3;" : "=l"(d) : "l"(a), "l"(b), "l"(c))

__device__ __forceinline__ void unpack2(ull v, float& lo, float& hi) {
    asm("mov.b64 {%0, %1}, %2;" : "=f"(lo), "=f"(hi) : "l"(v));
}

// ---------------- GEMM: C[r][m][h] = sum_k A[m][k] * B[r][k][h] (+bias) ----------------
// FFMA2 GEMM, M-paired accumulators. Block tile 128x128, K-chunk 32, 256 threads.
// Thread: rows r0=8*ty (ty=tid>>4), cols c0=8*tx (tx=tid&15).
// acc[p][j] = { C[r0+2p][c0+j], C[r0+2p+1][c0+j] }  (p=0..3, j=0..7)
// A operand: natural row-pairs from transposed tile Ast[k][row] (no duplication,
// uniform per half-warp -> broadcast LDS). B operand: duplicated {b,b} pairs.
__global__ void __launch_bounds__(256, 2)
gemm128(const float* __restrict__ A, const float* __restrict__ Bmat,
        float* __restrict__ C, int M,
        const float* __restrict__ qv, const float* __restrict__ kv,
        float* __restrict__ sq, float* __restrict__ sk,
        const float* __restrict__ bias)
{
    const int r = blockIdx.y;
    const float* B = Bmat + (size_t)r * HH * HH;
    float* Cr = C + (size_t)r * M * HH;
    const int row0 = blockIdx.x * 128;
    const int tid = threadIdx.x;
    const int tx = tid & 15;   // 16 col groups of 8
    const int ty = tid >> 4;   // 16 row groups of 8

    __shared__ float Ast[32][136];   // transposed A tile: Ast[k][row]
    __shared__ ull   Bs2[32][130];   // duplicated B tile: Bs2[k][col] = {b,b}

    ull acc[4][8];
#pragma unroll
    for (int p = 0; p < 4; p++)
#pragma unroll
        for (int j = 0; j < 8; j++) acc[p][j] = 0ull;

    const int r0 = ty << 3;
    const int c0 = tx << 3;

    for (int k0 = 0; k0 < 128; k0 += 32) {
        // ---- load A tile 128x32, transpose into Ast[k][row] ----
        {
            int row = tid >> 1;            // 0..127
            int kb = (tid & 1) << 4;       // 0 or 16
            int gr = row0 + row;
            float4 v0 = make_float4(0.f,0.f,0.f,0.f), v1 = v0, v2 = v0, v3 = v0;
            if (gr < M) {
                const float4* ap = reinterpret_cast<const float4*>(A + (size_t)gr * 128 + k0 + kb);
                v0 = ap[0]; v1 = ap[1]; v2 = ap[2]; v3 = ap[3];
            }
            Ast[kb +  0][row] = v0.x; Ast[kb +  1][row] = v0.y;
            Ast[kb +  2][row] = v0.z; Ast[kb +  3][row] = v0.w;
            Ast[kb +  4][row] = v1.x; Ast[kb +  5][row] = v1.y;
            Ast[kb +  6][row] = v1.z; Ast[kb +  7][row] = v1.w;
            Ast[kb +  8][row] = v2.x; Ast[kb +  9][row] = v2.y;
            Ast[kb + 10][row] = v2.z; Ast[kb + 11][row] = v2.w;
            Ast[kb + 12][row] = v3.x; Ast[kb + 13][row] = v3.y;
            Ast[kb + 14][row] = v3.z; Ast[kb + 15][row] = v3.w;
        }
        // ---- load B tile 32x128, store duplicated {b,b} ----
#pragma unroll
        for (int it = 0; it < 4; it++) {
            int idx = tid + it * 256;
            int krow = idx >> 5;
            int c4 = (idx & 31) << 2;
            float4 v = *reinterpret_cast<const float4*>(B + (size_t)(k0 + krow) * 128 + c4);
            float4* dst = reinterpret_cast<float4*>(&Bs2[krow][c4]);
            dst[0] = make_float4(v.x, v.x, v.y, v.y);
            dst[1] = make_float4(v.z, v.z, v.w, v.w);
        }
        __syncthreads();

#pragma unroll 8
        for (int k = 0; k < 32; k++) {
            // A: rows r0..r0+7 as 4 natural pairs (uniform per half-warp)
            float4 a03 = *reinterpret_cast<const float4*>(&Ast[k][r0]);
            float4 a47 = *reinterpret_cast<const float4*>(&Ast[k][r0 + 4]);
            ull ap[4];
            asm("mov.b64 %0, {%1, %2};" : "=l"(ap[0]) : "f"(a03.x), "f"(a03.y));
            asm("mov.b64 %0, {%1, %2};" : "=l"(ap[1]) : "f"(a03.z), "f"(a03.w));
            asm("mov.b64 %0, {%1, %2};" : "=l"(ap[2]) : "f"(a47.x), "f"(a47.y));
            asm("mov.b64 %0, {%1, %2};" : "=l"(ap[3]) : "f"(a47.z), "f"(a47.w));
            // B: cols c0..c0+7 duplicated pairs
            ulonglong2 b01 = *reinterpret_cast<const ulonglong2*>(&Bs2[k][c0]);
            ulonglong2 b23 = *reinterpret_cast<const ulonglong2*>(&Bs2[k][c0 + 2]);
            ulonglong2 b45 = *reinterpret_cast<const ulonglong2*>(&Bs2[k][c0 + 4]);
            ulonglong2 b67 = *reinterpret_cast<const ulonglong2*>(&Bs2[k][c0 + 6]);
            ull bd[8] = { b01.x, b01.y, b23.x, b23.y, b45.x, b45.y, b67.x, b67.y };
#pragma unroll
            for (int p = 0; p < 4; p++) {
#pragma unroll
                for (int j = 0; j < 8; j++) {
                    FMA2(acc[p][j], ap[p], bd[j], acc[p][j]);
                }
            }
        }
        __syncthreads();
    }

    // ---- epilogue ----
    float q8[8], k8[8], bb8[8];
    if (qv) {
#pragma unroll
        for (int j = 0; j < 8; j++) { q8[j] = qv[c0 + j]; k8[j] = kv[c0 + j]; }
    }
    if (bias) {
#pragma unroll
        for (int j = 0; j < 8; j++) bb8[j] = bias[c0 + j];
    }

#pragma unroll
    for (int p = 0; p < 4; p++) {
        float clo[8], chi[8];
#pragma unroll
        for (int j = 0; j < 8; j++) unpack2(acc[p][j], clo[j], chi[j]);
        if (bias) {
#pragma unroll
            for (int j = 0; j < 8; j++) { clo[j] += bb8[j]; chi[j] += bb8[j]; }
        }
        int gr_lo = row0 + r0 + 2 * p;
        int gr_hi = gr_lo + 1;
        if (gr_lo < M) {
            float4* cp = reinterpret_cast<float4*>(Cr + (size_t)gr_lo * 128 + c0);
            cp[0] = make_float4(clo[0], clo[1], clo[2], clo[3]);
            cp[1] = make_float4(clo[4], clo[5], clo[6], clo[7]);
        }
        if (gr_hi < M) {
            float4* cp = reinterpret_cast<float4*>(Cr + (size_t)gr_hi * 128 + c0);
            cp[0] = make_float4(chi[0], chi[1], chi[2], chi[3]);
            cp[1] = make_float4(chi[4], chi[5], chi[6], chi[7]);
        }
        if (qv) {
            float pq_lo = 0.f, pk_lo = 0.f, pq_hi = 0.f, pk_hi = 0.f;
#pragma unroll
            for (int j = 0; j < 8; j++) {
                pq_lo += clo[j] * q8[j]; pk_lo += clo[j] * k8[j];
                pq_hi += chi[j] * q8[j]; pk_hi += chi[j] * k8[j];
            }
#pragma unroll
            for (int off = 8; off > 0; off >>= 1) {
                pq_lo += __shfl_down_sync(0xffffffffu, pq_lo, off, 16);
                pk_lo += __shfl_down_sync(0xffffffffu, pk_lo, off, 16);
                pq_hi += __shfl_down_sync(0xffffffffu, pq_hi, off, 16);
                pk_hi += __shfl_down_sync(0xffffffffu, pk_hi, off, 16);
            }
            if (tx == 0) {
                if (gr_lo < M) {
                    sq[(size_t)r * M + gr_lo] = pq_lo;
                    sk[(size_t)r * M + gr_lo] = pk_lo;
                }
                if (gr_hi < M) {
                    sq[(size_t)r * M + gr_hi] = pq_hi;
                    sk[(size_t)r * M + gr_hi] = pk_hi;
                }
            }
        }
    }
}

// ---------------- CSR build (tgt is identical across both layers) ----------------
__global__ void zero_counts_kernel() {
    int n = blockIdx.x * blockDim.x + threadIdx.x;
    if (n < NN) g_counts[n] = 0;
}
__global__ void hist_kernel(const int* __restrict__ tgt) {
    int e = blockIdx.x * blockDim.x + threadIdx.x;
    if (e < EE) atomicAdd(&g_counts[tgt[e]], 1);
}
__global__ void scan_kernel() {
    __shared__ int part[1024];
    const int tid = threadIdx.x;
    const int CH = (NN + 1023) / 1024;
    const int st = tid * CH;
    int s = 0;
    for (int i = 0; i < CH; i++) {
        int idx = st + i;
        if (idx < NN) s += g_counts[idx];
    }
    part[tid] = s;
    __syncthreads();
    for (int off = 1; off < 1024; off <<= 1) {
        int add = (tid >= off) ? part[tid - off] : 0;
        __syncthreads();
        part[tid] += add;
        __syncthreads();
    }
    int run = (tid == 0) ? 0 : part[tid - 1];
    for (int i = 0; i < CH; i++) {
        int idx = st + i;
        if (idx < NN) {
            g_off[idx] = run;
            run += g_counts[idx];
        }
    }
    if (tid == 1023) g_off[NN] = part[1023];
}
__global__ void copy_cursor_kernel() {
    int n = blockIdx.x * blockDim.x + threadIdx.x;
    if (n < NN) g_cursor[n] = g_off[n];
}
__global__ void scatter_kernel(const int* __restrict__ tgt) {
    int e = blockIdx.x * blockDim.x + threadIdx.x;
    if (e < EE) {
        int pos = atomicAdd(&g_cursor[tgt[e]], 1);
        g_sorted[pos] = e;
    }
}

// ---------------- attention logits + segment max ----------------
__global__ void minit_kernel() {
    int n = blockIdx.x * blockDim.x + threadIdx.x;
    if (n < NN) g_menc[n] = 0u;
}
__global__ void alpha_kernel(const int* __restrict__ src, const int* __restrict__ tgt,
                             const int* __restrict__ et)
{
    int e = blockIdx.x * blockDim.x + threadIdx.x;
    if (e >= EE) return;
    int t = tgt[e], s = src[e], r = et[e];
    float a = g_sq[r * NN + t] + g_sk[r * NN + s];
    a = (a > 0.f) ? a : 0.2f * a;
    g_alpha[e] = a;
    atomicMax(&g_menc[t], fenc(a));
}

// ---------------- per-node softmax + weighted aggregation (no feature atomics) -------
__global__ void agg_kernel(const int* __restrict__ src, const int* __restrict__ et,
                           const float* __restrict__ bias, float* __restrict__ Y)
{
    const int n = blockIdx.x;
    const int h = threadIdx.x;  // 128
    const int beg = g_off[n], end = g_off[n + 1];
    const float m = fdec(g_menc[n]);
    float acc = 0.f, den = 0.f;
    for (int i = beg; i < end; i++) {
        int e = g_sorted[i];
        float w = __expf(g_alpha[e] - m);
        int s = src[e];
        int r = et[e];
        den += w;
        acc += w * g_xw[((size_t)r * NN + s) * HH + h];
    }
    float v = acc / (den + 1e-16f) + bias[h];
    v = fmaxf(v, 0.f);  // both RGAT layers are followed by ReLU
    Y[(size_t)n * HH + h] = v;
}

// ---------------- Wl transpose (final linear uses h @ Wl^T) ----------------
__global__ void transpose_kernel(const float* __restrict__ Wl) {
    int idx = blockIdx.x * blockDim.x + threadIdx.x;  // 16384
    if (idx < HH * HH) {
        int o = idx / HH, hc = idx % HH;
        g_wlt[hc * HH + o] = Wl[o * HH + hc];
    }
}

// ---------------- launch ----------------
extern "C" void kernel_launch(void* const* d_in, const int* in_sizes, int n_in,
                              void* d_out, int out_size)
{
    const float* x  = (const float*)d_in[0];
    const int*   ei = (const int*)d_in[1];
    const int*   et = (const int*)d_in[2];
    // d_in[3] = batch (unused: equal-size sorted graphs -> plain reshape)
    const float* W1 = (const float*)d_in[4];
    const float* q1 = (const float*)d_in[5];
    const float* k1 = (const float*)d_in[6];
    const float* b1 = (const float*)d_in[7];
    const float* W2 = (const float*)d_in[8];
    const float* q2 = (const float*)d_in[9];
    const float* k2 = (const float*)d_in[10];
    const float* b2 = (const float*)d_in[11];
    const float* Wl = (const float*)d_in[12];
    const float* bl = (const float*)d_in[13];
    const int* src = ei;
    const int* tgt = ei + EE;

    float *p_xw, *p_h1, *p_h2, *p_wlt, *p_sq, *p_sk;
    cudaGetSymbolAddress((void**)&p_xw, g_xw);
    cudaGetSymbolAddress((void**)&p_h1, g_h1);
    cudaGetSymbolAddress((void**)&p_h2, g_h2);
    cudaGetSymbolAddress((void**)&p_wlt, g_wlt);
    cudaGetSymbolAddress((void**)&p_sq, g_sq);
    cudaGetSymbolAddress((void**)&p_sk, g_sk);

    const int EB = (EE + 255) / 256;
    const int NB = (NN + 255) / 256;
    const int MB = (NN + 127) / 128;

    // CSR by target (shared by both layers)
    zero_counts_kernel<<<NB, 256>>>();
    hist_kernel<<<EB, 256>>>(tgt);
    scan_kernel<<<1, 1024>>>();
    copy_cursor_kernel<<<NB, 256>>>();
    scatter_kernel<<<EB, 256>>>(tgt);

    transpose_kernel<<<(HH * HH + 255) / 256, 256>>>(Wl);

    // ---- layer 1 ----
    gemm128<<<dim3(MB, RR), 256>>>(x, W1, p_xw, NN, q1, k1, p_sq, p_sk, nullptr);
    minit_kernel<<<NB, 256>>>();
    alpha_kernel<<<EB, 256>>>(src, tgt, et);
    agg_kernel<<<NN, HH>>>(src, et, b1, p_h1);

    // ---- layer 2 ----
    gemm128<<<dim3(MB, RR), 256>>>(p_h1, W2, p_xw, NN, q2, k2, p_sq, p_sk, nullptr);
    minit_kernel<<<NB, 256>>>();
    alpha_kernel<<<EB, 256>>>(src, tgt, et);
    agg_kernel<<<NN, HH>>>(src, et, b2, p_h2);

    // ---- final linear straight into d_out ([B,NPG,H] is contiguous [N,H]) ----
    gemm128<<<dim3(MB, 1), 256>>>(p_h2, p_wlt, (float*)d_out, NN,
                                  nullptr, nullptr, nullptr, nullptr, bl);
}

// round 8
// speedup vs baseline: 1.9790x; 1.9790x over previous
#include <cuda_runtime.h>
#include <cuda_bf16.h>

#define NN 50000
#define EE 800000
#define RR 8
#define HH 128

// ---------------- scratch (device globals; no allocation allowed) ----------------
__device__ float    g_xw[(size_t)RR * NN * HH];   // per-relation transformed features
__device__ float    g_sq[RR * NN];
__device__ float    g_sk[RR * NN];
__device__ float    g_alpha[EE];
__device__ unsigned g_menc[NN];
__device__ float    g_h1[(size_t)NN * HH];
__device__ float    g_h2[(size_t)NN * HH];
__device__ int      g_counts[NN];
__device__ int      g_off[NN + 1];
__device__ int      g_cursor[NN];
__device__ int      g_sorted[EE];
__device__ float    g_wlt[HH * HH];
__device__ float    g_pq[RR * HH];
__device__ float    g_pk[RR * HH];

// ---------------- helpers ----------------
__device__ __forceinline__ unsigned fenc(float f) {
    unsigned u = __float_as_uint(f);
    return (u & 0x80000000u) ? ~u : (u | 0x80000000u);
}
__device__ __forceinline__ float fdec(unsigned u) {
    unsigned b = (u & 0x80000000u) ? (u ^ 0x80000000u) : ~u;
    return __uint_as_float(b);
}
__device__ __forceinline__ float tf32_rna(float x) {
    unsigned r;
    asm("cvt.rna.tf32.f32 %0, %1;" : "=r"(r) : "f"(x));
    return __uint_as_float(r);
}
// split x into hi (tf32) and lo (tf32 of residual)
__device__ __forceinline__ void tf32_split(float x, float& hi, float& lo) {
    hi = tf32_rna(x);
    lo = tf32_rna(x - hi);
}

#define MMA_TF32(C, A0, A1, A2, A3, B0, B1)                                         \
    asm volatile("mma.sync.aligned.m16n8k8.row.col.f32.tf32.tf32.f32 "             \
                 "{%0,%1,%2,%3}, {%4,%5,%6,%7}, {%8,%9}, {%0,%1,%2,%3};"           \
                 : "+f"((C)[0]), "+f"((C)[1]), "+f"((C)[2]), "+f"((C)[3])          \
                 : "r"(A0), "r"(A1), "r"(A2), "r"(A3), "r"(B0), "r"(B1))

// ---------------- 3xTF32 mma GEMM: C[r] = A @ B[r] (+bias) ----------------
// Block tile 128x128, K-chunk 32 (4 k-steps of 8), 128 threads = 4 warps (2x2).
// Warp tile 64x64: 4 m16-tiles x 8 n8-tiles.
// smem layout (dynamic): As4[kstep 4][m 128][slot 5(4 used)] float4, Bs4 same for n.
// slot c holds {hi(k=c), hi(k=c+4), lo(k=c), lo(k=c+4)} -> one LDS.128 per fragment.
__global__ void __launch_bounds__(128)
gemm_mma(const float* __restrict__ A, const float* __restrict__ Bmat,
         float* __restrict__ C, int M, const float* __restrict__ bias)
{
    extern __shared__ float4 sm4[];
    float4* As4 = sm4;                  // 4*128*5 = 2560 float4
    float4* Bs4 = sm4 + 2560;

    const int r = blockIdx.y;
    const float* B = Bmat + (size_t)r * HH * HH;
    float* Cr = C + (size_t)r * M * HH;
    const int row0 = blockIdx.x * 128;
    const int tid = threadIdx.x;
    const int lane = tid & 31;
    const int wid = tid >> 5;
    const int warp_m = (wid & 1) << 6;   // 0 or 64
    const int warp_n = (wid >> 1) << 6;  // 0 or 64
    const int g  = lane >> 2;            // 0..7
    const int cq = lane & 3;             // 0..3

    float acc[4][8][4];
#pragma unroll
    for (int mt = 0; mt < 4; mt++)
#pragma unroll
        for (int nt = 0; nt < 8; nt++)
#pragma unroll
            for (int j = 0; j < 4; j++) acc[mt][nt][j] = 0.f;

    for (int k0 = 0; k0 < 128; k0 += 32) {
        // ---- load + split A tile: thread tid owns row tid ----
        {
            const int gr = row0 + tid;
            const float4* ap = reinterpret_cast<const float4*>(A + (size_t)gr * HH + k0);
            const float4 z4 = make_float4(0.f, 0.f, 0.f, 0.f);
#pragma unroll
            for (int ks = 0; ks < 4; ks++) {
                float4 u = z4, v = z4;
                if (gr < M) { u = ap[ks * 2]; v = ap[ks * 2 + 1]; }
                float uh[4], ul[4], vh[4], vl[4];
                tf32_split(u.x, uh[0], ul[0]); tf32_split(u.y, uh[1], ul[1]);
                tf32_split(u.z, uh[2], ul[2]); tf32_split(u.w, uh[3], ul[3]);
                tf32_split(v.x, vh[0], vl[0]); tf32_split(v.y, vh[1], vl[1]);
                tf32_split(v.z, vh[2], vl[2]); tf32_split(v.w, vh[3], vl[3]);
                float4* dst = &As4[(ks * 128 + tid) * 5];
#pragma unroll
                for (int c = 0; c < 4; c++)
                    dst[c] = make_float4(uh[c], vh[c], ul[c], vl[c]);
            }
        }
        // ---- load + split B tile: thread tid owns column n = tid ----
        {
#pragma unroll
            for (int ks = 0; ks < 4; ks++) {
                float e[8];
#pragma unroll
                for (int kk = 0; kk < 8; kk++)
                    e[kk] = B[(size_t)(k0 + ks * 8 + kk) * HH + tid];
                float4* dst = &Bs4[(ks * 128 + tid) * 5];
#pragma unroll
                for (int c = 0; c < 4; c++) {
                    float h0, l0, h1, l1;
                    tf32_split(e[c], h0, l0);
                    tf32_split(e[c + 4], h1, l1);
                    dst[c] = make_float4(h0, h1, l0, l1);
                }
            }
        }
        __syncthreads();

#pragma unroll
        for (int ks = 0; ks < 4; ks++) {
            // B fragments for all 8 n-tiles
            unsigned bh[8][2], bl[8][2];
#pragma unroll
            for (int nt = 0; nt < 8; nt++) {
                float4 w = Bs4[(ks * 128 + warp_n + nt * 8 + g) * 5 + cq];
                bh[nt][0] = __float_as_uint(w.x); bh[nt][1] = __float_as_uint(w.y);
                bl[nt][0] = __float_as_uint(w.z); bl[nt][1] = __float_as_uint(w.w);
            }
#pragma unroll
            for (int mt = 0; mt < 4; mt++) {
                float4 v1 = As4[(ks * 128 + warp_m + mt * 16 + g) * 5 + cq];
                float4 v2 = As4[(ks * 128 + warp_m + mt * 16 + 8 + g) * 5 + cq];
                unsigned ah0 = __float_as_uint(v1.x), ah1 = __float_as_uint(v2.x);
                unsigned ah2 = __float_as_uint(v1.y), ah3 = __float_as_uint(v2.y);
                unsigned al0 = __float_as_uint(v1.z), al1 = __float_as_uint(v2.z);
                unsigned al2 = __float_as_uint(v1.w), al3 = __float_as_uint(v2.w);
#pragma unroll
                for (int nt = 0; nt < 8; nt++)
                    MMA_TF32(acc[mt][nt], ah0, ah1, ah2, ah3, bh[nt][0], bh[nt][1]);
#pragma unroll
                for (int nt = 0; nt < 8; nt++)
                    MMA_TF32(acc[mt][nt], ah0, ah1, ah2, ah3, bl[nt][0], bl[nt][1]);
#pragma unroll
                for (int nt = 0; nt < 8; nt++)
                    MMA_TF32(acc[mt][nt], al0, al1, al2, al3, bh[nt][0], bh[nt][1]);
            }
        }
        __syncthreads();
    }

    // ---- epilogue ----
#pragma unroll
    for (int mt = 0; mt < 4; mt++) {
        int r_lo = row0 + warp_m + mt * 16 + g;
        int r_hi = r_lo + 8;
#pragma unroll
        for (int nt = 0; nt < 8; nt++) {
            int col = warp_n + nt * 8 + 2 * cq;
            float b0v = 0.f, b1v = 0.f;
            if (bias) { b0v = bias[col]; b1v = bias[col + 1]; }
            if (r_lo < M) {
                float2* p = reinterpret_cast<float2*>(Cr + (size_t)r_lo * HH + col);
                *p = make_float2(acc[mt][nt][0] + b0v, acc[mt][nt][1] + b1v);
            }
            if (r_hi < M) {
                float2* p = reinterpret_cast<float2*>(Cr + (size_t)r_hi * HH + col);
                *p = make_float2(acc[mt][nt][2] + b0v, acc[mt][nt][3] + b1v);
            }
        }
    }
}

// ---------------- attention projection vectors: P[r] = W[r] @ q (and @ k) ----------------
// one warp per (r, i) pair; 256 thr = 8 warps; grid 128 blocks -> 1024 warps = RR*HH.
__global__ void proj_kernel(const float* __restrict__ W, const float* __restrict__ qv,
                            const float* __restrict__ kv,
                            float* __restrict__ Pq, float* __restrict__ Pk)
{
    int warp = (blockIdx.x * blockDim.x + threadIdx.x) >> 5;
    int lane = threadIdx.x & 31;
    int r = warp >> 7, i = warp & 127;
    const float* wrow = W + ((size_t)r * HH + i) * HH;
    float aq = 0.f, ak = 0.f;
#pragma unroll
    for (int o = 0; o < 4; o++) {
        float w = wrow[lane + o * 32];
        aq += w * qv[lane + o * 32];
        ak += w * kv[lane + o * 32];
    }
#pragma unroll
    for (int off = 16; off > 0; off >>= 1) {
        aq += __shfl_down_sync(0xffffffffu, aq, off);
        ak += __shfl_down_sync(0xffffffffu, ak, off);
    }
    if (lane == 0) { Pq[r * HH + i] = aq; Pk[r * HH + i] = ak; }
}

// ---------------- sq[r][n] = X[n] . Pq[r] ; sk likewise (exact fp32) ----------------
__global__ void sqsk_kernel(const float* __restrict__ X)
{
    __shared__ float sPq[RR * HH], sPk[RR * HH];
    for (int i = threadIdx.x; i < RR * HH; i += 128) {
        sPq[i] = g_pq[i];
        sPk[i] = g_pk[i];
    }
    __syncthreads();
    int n = blockIdx.x * 4 + (threadIdx.x >> 5);
    if (n >= NN) return;
    int lane = threadIdx.x & 31;
    float x0 = X[(size_t)n * HH + lane];
    float x1 = X[(size_t)n * HH + lane + 32];
    float x2 = X[(size_t)n * HH + lane + 64];
    float x3 = X[(size_t)n * HH + lane + 96];
#pragma unroll
    for (int r = 0; r < RR; r++) {
        const float* pq = &sPq[r * HH];
        const float* pk = &sPk[r * HH];
        float aq = x0 * pq[lane] + x1 * pq[lane + 32] + x2 * pq[lane + 64] + x3 * pq[lane + 96];
        float ak = x0 * pk[lane] + x1 * pk[lane + 32] + x2 * pk[lane + 64] + x3 * pk[lane + 96];
#pragma unroll
        for (int off = 16; off > 0; off >>= 1) {
            aq += __shfl_down_sync(0xffffffffu, aq, off);
            ak += __shfl_down_sync(0xffffffffu, ak, off);
        }
        if (lane == 0) { g_sq[r * NN + n] = aq; g_sk[r * NN + n] = ak; }
    }
}

// ---------------- CSR build (tgt is identical across both layers) ----------------
__global__ void zero_counts_kernel() {
    int n = blockIdx.x * blockDim.x + threadIdx.x;
    if (n < NN) g_counts[n] = 0;
}
__global__ void hist_kernel(const int* __restrict__ tgt) {
    int e = blockIdx.x * blockDim.x + threadIdx.x;
    if (e < EE) atomicAdd(&g_counts[tgt[e]], 1);
}
__global__ void scan_kernel() {
    __shared__ int part[1024];
    const int tid = threadIdx.x;
    const int CH = (NN + 1023) / 1024;
    const int st = tid * CH;
    int s = 0;
    for (int i = 0; i < CH; i++) {
        int idx = st + i;
        if (idx < NN) s += g_counts[idx];
    }
    part[tid] = s;
    __syncthreads();
    for (int off = 1; off < 1024; off <<= 1) {
        int add = (tid >= off) ? part[tid - off] : 0;
        __syncthreads();
        part[tid] += add;
        __syncthreads();
    }
    int run = (tid == 0) ? 0 : part[tid - 1];
    for (int i = 0; i < CH; i++) {
        int idx = st + i;
        if (idx < NN) {
            g_off[idx] = run;
            run += g_counts[idx];
        }
    }
    if (tid == 1023) g_off[NN] = part[1023];
}
__global__ void copy_cursor_kernel() {
    int n = blockIdx.x * blockDim.x + threadIdx.x;
    if (n < NN) g_cursor[n] = g_off[n];
}
__global__ void scatter_kernel(const int* __restrict__ tgt) {
    int e = blockIdx.x * blockDim.x + threadIdx.x;
    if (e < EE) {
        int pos = atomicAdd(&g_cursor[tgt[e]], 1);
        g_sorted[pos] = e;
    }
}

// ---------------- attention logits + segment max ----------------
__global__ void minit_kernel() {
    int n = blockIdx.x * blockDim.x + threadIdx.x;
    if (n < NN) g_menc[n] = 0u;
}
__global__ void alpha_kernel(const int* __restrict__ src, const int* __restrict__ tgt,
                             const int* __restrict__ et)
{
    int e = blockIdx.x * blockDim.x + threadIdx.x;
    if (e >= EE) return;
    int t = tgt[e], s = src[e], r = et[e];
    float a = g_sq[r * NN + t] + g_sk[r * NN + s];
    a = (a > 0.f) ? a : 0.2f * a;
    g_alpha[e] = a;
    atomicMax(&g_menc[t], fenc(a));
}

// ---------------- per-node softmax + weighted aggregation (no feature atomics) -------
__global__ void agg_kernel(const int* __restrict__ src, const int* __restrict__ et,
                           const float* __restrict__ bias, float* __restrict__ Y)
{
    const int n = blockIdx.x;
    const int h = threadIdx.x;  // 128
    const int beg = g_off[n], end = g_off[n + 1];
    const float m = fdec(g_menc[n]);
    float acc = 0.f, den = 0.f;
    for (int i = beg; i < end; i++) {
        int e = g_sorted[i];
        float w = __expf(g_alpha[e] - m);
        int s = src[e];
        int r = et[e];
        den += w;
        acc += w * g_xw[((size_t)r * NN + s) * HH + h];
    }
    float v = acc / (den + 1e-16f) + bias[h];
    v = fmaxf(v, 0.f);  // both RGAT layers are followed by ReLU
    Y[(size_t)n * HH + h] = v;
}

// ---------------- Wl transpose (final linear uses h @ Wl^T) ----------------
__global__ void transpose_kernel(const float* __restrict__ Wl) {
    int idx = blockIdx.x * blockDim.x + threadIdx.x;  // 16384
    if (idx < HH * HH) {
        int o = idx / HH, hc = idx % HH;
        g_wlt[hc * HH + o] = Wl[o * HH + hc];
    }
}

// ---------------- launch ----------------
extern "C" void kernel_launch(void* const* d_in, const int* in_sizes, int n_in,
                              void* d_out, int out_size)
{
    const float* x  = (const float*)d_in[0];
    const int*   ei = (const int*)d_in[1];
    const int*   et = (const int*)d_in[2];
    // d_in[3] = batch (unused: equal-size sorted graphs -> plain reshape)
    const float* W1 = (const float*)d_in[4];
    const float* q1 = (const float*)d_in[5];
    const float* k1 = (const float*)d_in[6];
    const float* b1 = (const float*)d_in[7];
    const float* W2 = (const float*)d_in[8];
    const float* q2 = (const float*)d_in[9];
    const float* k2 = (const float*)d_in[10];
    const float* b2 = (const float*)d_in[11];
    const float* Wl = (const float*)d_in[12];
    const float* bl = (const float*)d_in[13];
    const int* src = ei;
    const int* tgt = ei + EE;

    float *p_xw, *p_h1, *p_h2, *p_wlt, *p_pq, *p_pk;
    cudaGetSymbolAddress((void**)&p_xw, g_xw);
    cudaGetSymbolAddress((void**)&p_h1, g_h1);
    cudaGetSymbolAddress((void**)&p_h2, g_h2);
    cudaGetSymbolAddress((void**)&p_wlt, g_wlt);
    cudaGetSymbolAddress((void**)&p_pq, g_pq);
    cudaGetSymbolAddress((void**)&p_pk, g_pk);

    const int SMEM_BYTES = 2 * 2560 * 16;  // 81920
    cudaFuncSetAttribute(gemm_mma, cudaFuncAttributeMaxDynamicSharedMemorySize, SMEM_BYTES);

    const int EB = (EE + 255) / 256;
    const int NB = (NN + 255) / 256;
    const int MB = (NN + 127) / 128;
    const int SQB = (NN + 3) / 4;

    // CSR by target (shared by both layers)
    zero_counts_kernel<<<NB, 256>>>();
    hist_kernel<<<EB, 256>>>(tgt);
    scan_kernel<<<1, 1024>>>();
    copy_cursor_kernel<<<NB, 256>>>();
    scatter_kernel<<<EB, 256>>>(tgt);

    transpose_kernel<<<(HH * HH + 255) / 256, 256>>>(Wl);

    // ---- layer 1 ----
    proj_kernel<<<128, 256>>>(W1, q1, k1, p_pq, p_pk);
    gemm_mma<<<dim3(MB, RR), 128, SMEM_BYTES>>>(x, W1, p_xw, NN, nullptr);
    sqsk_kernel<<<SQB, 128>>>(x);
    minit_kernel<<<NB, 256>>>();
    alpha_kernel<<<EB, 256>>>(src, tgt, et);
    agg_kernel<<<NN, HH>>>(src, et, b1, p_h1);

    // ---- layer 2 ----
    proj_kernel<<<128, 256>>>(W2, q2, k2, p_pq, p_pk);
    gemm_mma<<<dim3(MB, RR), 128, SMEM_BYTES>>>(p_h1, W2, p_xw, NN, nullptr);
    sqsk_kernel<<<SQB, 128>>>(p_h1);
    minit_kernel<<<NB, 256>>>();
    alpha_kernel<<<EB, 256>>>(src, tgt, et);
    agg_kernel<<<NN, HH>>>(src, et, b2, p_h2);

    // ---- final linear straight into d_out ([B,NPG,H] is contiguous [N,H]) ----
    gemm_mma<<<dim3(MB, 1), 128, SMEM_BYTES>>>(p_h2, p_wlt, (float*)d_out, NN, bl);
}

// round 11
// speedup vs baseline: 2.2246x; 1.1241x over previous
#include <cuda_runtime.h>
#include <cuda_bf16.h>

#define NN 50000
#define EE 800000
#define RR 8
#define HH 128
#define MBLK 391   // ceil(NN/128)

// ---------------- scratch (device globals; no allocation allowed) ----------------
__device__ float    g_xw[(size_t)RR * NN * HH];   // per-relation transformed features
__device__ float    g_sq[RR * NN];
__device__ float    g_sk[RR * NN];
__device__ float    g_alpha_s[EE];                // attention logits in slot (sorted) order
__device__ unsigned g_menc[NN];
__device__ float    g_h1[(size_t)NN * HH];
__device__ float    g_h2[(size_t)NN * HH];
__device__ int      g_counts[NN];
__device__ int      g_off[NN + 1];
__device__ int      g_cursor[NN];
__device__ int      g_pos[EE];                    // edge -> slot
__device__ int      g_rsrc[EE];                   // slot -> r*NN+src
__device__ float    g_wlt[HH * HH];
__device__ float    g_pq[RR * HH];
__device__ float    g_pk[RR * HH];
__device__ float4   g_asp[(size_t)MBLK * 4 * 2048];  // pre-split A, smem slot layout (51.2MB)
__device__ float4   g_bsp[RR * 4 * 2048];            // pre-split B (4MB)

// ---------------- helpers ----------------
__device__ __forceinline__ unsigned fenc(float f) {
    unsigned u = __float_as_uint(f);
    return (u & 0x80000000u) ? ~u : (u | 0x80000000u);
}
__device__ __forceinline__ float fdec(unsigned u) {
    unsigned b = (u & 0x80000000u) ? (u ^ 0x80000000u) : ~u;
    return __uint_as_float(b);
}
__device__ __forceinline__ float tf32_rna(float x) {
    unsigned r;
    asm("cvt.rna.tf32.f32 %0, %1;" : "=r"(r) : "f"(x));
    return __uint_as_float(r);
}
__device__ __forceinline__ void tf32_split(float x, float& hi, float& lo) {
    hi = tf32_rna(x);
    lo = tf32_rna(x - hi);
}

#define MMA_TF32(C, A0, A1, A2, A3, B0, B1)                                         \
    asm volatile("mma.sync.aligned.m16n8k8.row.col.f32.tf32.tf32.f32 "             \
                 "{%0,%1,%2,%3}, {%4,%5,%6,%7}, {%8,%9}, {%0,%1,%2,%3};"           \
                 : "+f"((C)[0]), "+f"((C)[1]), "+f"((C)[2]), "+f"((C)[3])          \
                 : "r"(A0), "r"(A1), "r"(A2), "r"(A3), "r"(B0), "r"(B1))

// ---------------- prep A: split into gemm smem slot layout, tiled by 128-row block ------
// layout: g_asp[(blk*4+kc)*2048 + (ks*128 + row)*4 + slot]
// slot c = {hi(k=c), hi(k=c+4), lo(k=c), lo(k=c+4)} within k-step ks (k = kc*32+ks*8+..)
__global__ void prep_a_kernel(const float* __restrict__ A, int M)
{
    const int tid = threadIdx.x;
    const int blk = blockIdx.x;
    const int grow = blk * 128 + tid;
    const float4 z4 = make_float4(0.f, 0.f, 0.f, 0.f);
    const float4* ap = reinterpret_cast<const float4*>(A + (size_t)grow * HH);
#pragma unroll
    for (int kc = 0; kc < 4; kc++) {
        float4* dst = g_asp + ((size_t)(blk * 4 + kc)) * 2048;
#pragma unroll
        for (int ks = 0; ks < 4; ks++) {
            float4 u = z4, v = z4;
            if (grow < M) { u = ap[kc * 8 + ks * 2]; v = ap[kc * 8 + ks * 2 + 1]; }
            float uh[4], ul[4], vh[4], vl[4];
            tf32_split(u.x, uh[0], ul[0]); tf32_split(u.y, uh[1], ul[1]);
            tf32_split(u.z, uh[2], ul[2]); tf32_split(u.w, uh[3], ul[3]);
            tf32_split(v.x, vh[0], vl[0]); tf32_split(v.y, vh[1], vl[1]);
            tf32_split(v.z, vh[2], vl[2]); tf32_split(v.w, vh[3], vl[3]);
#pragma unroll
            for (int c = 0; c < 4; c++)
                dst[(ks * 128 + tid) * 4 + c] = make_float4(uh[c], vh[c], ul[c], vl[c]);
        }
    }
}

// ---------------- prep B: same slot layout per (r, kc); blockIdx.x = r*4+kc ----------
__global__ void prep_b_kernel(const float* __restrict__ Bmat)
{
    const int r = blockIdx.x >> 2;
    const int kc = blockIdx.x & 3;
    const int n = threadIdx.x;
    float4* dst = g_bsp + (size_t)blockIdx.x * 2048;
#pragma unroll
    for (int ks = 0; ks < 4; ks++) {
        float e[8];
#pragma unroll
        for (int kk = 0; kk < 8; kk++)
            e[kk] = Bmat[(size_t)r * HH * HH + (size_t)(kc * 32 + ks * 8 + kk) * HH + n];
#pragma unroll
        for (int c = 0; c < 4; c++) {
            float h0, l0, h1, l1;
            tf32_split(e[c], h0, l0);
            tf32_split(e[c + 4], h1, l1);
            dst[(ks * 128 + n) * 4 + c] = make_float4(h0, h1, l0, l1);
        }
    }
}

// ---------------- 3xTF32 mma GEMM on pre-split operands ----------------
// Block tile 128x128, K-chunk 32 (4 k-steps of 8), 128 threads = 4 warps (2x2).
// smem: As4[kstep 4][m 128][slot 5(4 used)] float4 (pad slot 5 -> conflict-free LDS.128)
__global__ void __launch_bounds__(128)
gemm_mma(float* __restrict__ C, int M, const float* __restrict__ bias)
{
    extern __shared__ float4 sm4[];
    float4* As4 = sm4;                  // 2560 float4
    float4* Bs4 = sm4 + 2560;

    const int r = blockIdx.y;
    float* Cr = C + (size_t)r * M * HH;
    const int row0 = blockIdx.x * 128;
    const int tid = threadIdx.x;
    const int lane = tid & 31;
    const int wid = tid >> 5;
    const int warp_m = (wid & 1) << 6;   // 0 or 64
    const int warp_n = (wid >> 1) << 6;  // 0 or 64
    const int g  = lane >> 2;            // 0..7
    const int cq = lane & 3;             // 0..3

    float acc[4][8][4];
#pragma unroll
    for (int mt = 0; mt < 4; mt++)
#pragma unroll
        for (int nt = 0; nt < 8; nt++)
#pragma unroll
            for (int j = 0; j < 4; j++) acc[mt][nt][j] = 0.f;

#pragma unroll 1
    for (int kc = 0; kc < 4; kc++) {
        const float4* asrc = g_asp + ((size_t)(blockIdx.x * 4 + kc)) * 2048;
        const float4* bsrc = g_bsp + ((size_t)(r * 4 + kc)) * 2048;
#pragma unroll
        for (int it = 0; it < 16; it++) {
            int idx = tid + it * 128;
            int d = (idx >> 2) * 5 + (idx & 3);
            As4[d] = asrc[idx];
            Bs4[d] = bsrc[idx];
        }
        __syncthreads();

#pragma unroll
        for (int ks = 0; ks < 4; ks++) {
            unsigned bh[8][2], bl[8][2];
#pragma unroll
            for (int nt = 0; nt < 8; nt++) {
                float4 w = Bs4[(ks * 128 + warp_n + nt * 8 + g) * 5 + cq];
                bh[nt][0] = __float_as_uint(w.x); bh[nt][1] = __float_as_uint(w.y);
                bl[nt][0] = __float_as_uint(w.z); bl[nt][1] = __float_as_uint(w.w);
            }
#pragma unroll
            for (int mt = 0; mt < 4; mt++) {
                float4 v1 = As4[(ks * 128 + warp_m + mt * 16 + g) * 5 + cq];
                float4 v2 = As4[(ks * 128 + warp_m + mt * 16 + 8 + g) * 5 + cq];
                unsigned ah0 = __float_as_uint(v1.x), ah1 = __float_as_uint(v2.x);
                unsigned ah2 = __float_as_uint(v1.y), ah3 = __float_as_uint(v2.y);
                unsigned al0 = __float_as_uint(v1.z), al1 = __float_as_uint(v2.z);
                unsigned al2 = __float_as_uint(v1.w), al3 = __float_as_uint(v2.w);
#pragma unroll
                for (int nt = 0; nt < 8; nt++)
                    MMA_TF32(acc[mt][nt], ah0, ah1, ah2, ah3, bh[nt][0], bh[nt][1]);
#pragma unroll
                for (int nt = 0; nt < 8; nt++)
                    MMA_TF32(acc[mt][nt], ah0, ah1, ah2, ah3, bl[nt][0], bl[nt][1]);
#pragma unroll
                for (int nt = 0; nt < 8; nt++)
                    MMA_TF32(acc[mt][nt], al0, al1, al2, al3, bh[nt][0], bh[nt][1]);
            }
        }
        __syncthreads();
    }

    // ---- epilogue ----
#pragma unroll
    for (int mt = 0; mt < 4; mt++) {
        int r_lo = row0 + warp_m + mt * 16 + g;
        int r_hi = r_lo + 8;
#pragma unroll
        for (int nt = 0; nt < 8; nt++) {
            int col = warp_n + nt * 8 + 2 * cq;
            float b0v = 0.f, b1v = 0.f;
            if (bias) { b0v = bias[col]; b1v = bias[col + 1]; }
            if (r_lo < M) {
                float2* p = reinterpret_cast<float2*>(Cr + (size_t)r_lo * HH + col);
                *p = make_float2(acc[mt][nt][0] + b0v, acc[mt][nt][1] + b1v);
            }
            if (r_hi < M) {
                float2* p = reinterpret_cast<float2*>(Cr + (size_t)r_hi * HH + col);
                *p = make_float2(acc[mt][nt][2] + b0v, acc[mt][nt][3] + b1v);
            }
        }
    }
}

// ---------------- attention projection vectors: P[r] = W[r] @ q (and @ k) ----------------
__global__ void proj_kernel(const float* __restrict__ W, const float* __restrict__ qv,
                            const float* __restrict__ kv,
                            float* __restrict__ Pq, float* __restrict__ Pk)
{
    int warp = (blockIdx.x * blockDim.x + threadIdx.x) >> 5;
    int lane = threadIdx.x & 31;
    int r = warp >> 7, i = warp & 127;
    const float* wrow = W + ((size_t)r * HH + i) * HH;
    float aq = 0.f, ak = 0.f;
#pragma unroll
    for (int o = 0; o < 4; o++) {
        float w = wrow[lane + o * 32];
        aq += w * qv[lane + o * 32];
        ak += w * kv[lane + o * 32];
    }
#pragma unroll
    for (int off = 16; off > 0; off >>= 1) {
        aq += __shfl_down_sync(0xffffffffu, aq, off);
        ak += __shfl_down_sync(0xffffffffu, ak, off);
    }
    if (lane == 0) { Pq[r * HH + i] = aq; Pk[r * HH + i] = ak; }
}

// ---------------- sq[r][n] = X[n] . Pq[r] ; sk likewise (exact fp32) ----------------
__global__ void sqsk_kernel(const float* __restrict__ X)
{
    __shared__ float sPq[RR * HH], sPk[RR * HH];
    for (int i = threadIdx.x; i < RR * HH; i += 128) {
        sPq[i] = g_pq[i];
        sPk[i] = g_pk[i];
    }
    __syncthreads();
    int n = blockIdx.x * 4 + (threadIdx.x >> 5);
    if (n >= NN) return;
    int lane = threadIdx.x & 31;
    float x0 = X[(size_t)n * HH + lane];
    float x1 = X[(size_t)n * HH + lane + 32];
    float x2 = X[(size_t)n * HH + lane + 64];
    float x3 = X[(size_t)n * HH + lane + 96];
#pragma unroll
    for (int r = 0; r < RR; r++) {
        const float* pq = &sPq[r * HH];
        const float* pk = &sPk[r * HH];
        float aq = x0 * pq[lane] + x1 * pq[lane + 32] + x2 * pq[lane + 64] + x3 * pq[lane + 96];
        float ak = x0 * pk[lane] + x1 * pk[lane + 32] + x2 * pk[lane + 64] + x3 * pk[lane + 96];
#pragma unroll
        for (int off = 16; off > 0; off >>= 1) {
            aq += __shfl_down_sync(0xffffffffu, aq, off);
            ak += __shfl_down_sync(0xffffffffu, ak, off);
        }
        if (lane == 0) { g_sq[r * NN + n] = aq; g_sk[r * NN + n] = ak; }
    }
}

// ---------------- CSR build (tgt is identical across both layers) ----------------
__global__ void zero_counts_kernel() {
    int n = blockIdx.x * blockDim.x + threadIdx.x;
    if (n < NN) g_counts[n] = 0;
}
__global__ void hist_kernel(const int* __restrict__ tgt) {
    int e = blockIdx.x * blockDim.x + threadIdx.x;
    if (e < EE) atomicAdd(&g_counts[tgt[e]], 1);
}
__global__ void scan_kernel() {
    __shared__ int part[1024];
    const int tid = threadIdx.x;
    const int CH = (NN + 1023) / 1024;
    const int st = tid * CH;
    int s = 0;
    for (int i = 0; i < CH; i++) {
        int idx = st + i;
        if (idx < NN) s += g_counts[idx];
    }
    part[tid] = s;
    __syncthreads();
    for (int off = 1; off < 1024; off <<= 1) {
        int add = (tid >= off) ? part[tid - off] : 0;
        __syncthreads();
        part[tid] += add;
        __syncthreads();
    }
    int run = (tid == 0) ? 0 : part[tid - 1];
    for (int i = 0; i < CH; i++) {
        int idx = st + i;
        if (idx < NN) {
            g_off[idx] = run;
            run += g_counts[idx];
        }
    }
    if (tid == 1023) g_off[NN] = part[1023];
}
__global__ void copy_cursor_kernel() {
    int n = blockIdx.x * blockDim.x + threadIdx.x;
    if (n < NN) g_cursor[n] = g_off[n];
}
__global__ void scatter_kernel(const int* __restrict__ src, const int* __restrict__ tgt,
                               const int* __restrict__ et) {
    int e = blockIdx.x * blockDim.x + threadIdx.x;
    if (e < EE) {
        int pos = atomicAdd(&g_cursor[tgt[e]], 1);
        g_pos[e] = pos;
        g_rsrc[pos] = et[e] * NN + src[e];
    }
}

// ---------------- attention logits + segment max ----------------
__global__ void minit_kernel() {
    int n = blockIdx.x * blockDim.x + threadIdx.x;
    if (n < NN) g_menc[n] = 0u;
}
__global__ void alpha_kernel(const int* __restrict__ src, const int* __restrict__ tgt,
                             const int* __restrict__ et)
{
    int e = blockIdx.x * blockDim.x + threadIdx.x;
    if (e >= EE) return;
    int t = tgt[e], s = src[e], r = et[e];
    float a = g_sq[r * NN + t] + g_sk[r * NN + s];
    a = (a > 0.f) ? a : 0.2f * a;
    g_alpha_s[g_pos[e]] = a;
    atomicMax(&g_menc[t], fenc(a));
}

// ---------------- per-node softmax + weighted aggregation (no feature atomics) -------
__global__ void agg_kernel(const float* __restrict__ bias, float* __restrict__ Y)
{
    const int n = blockIdx.x;
    const int h = threadIdx.x;  // 128
    const int beg = g_off[n], end = g_off[n + 1];
    const float m = fdec(g_menc[n]);
    float acc = 0.f, den = 0.f;
    for (int i = beg; i < end; i++) {
        float a = g_alpha_s[i];
        int ad = g_rsrc[i];
        float w = __expf(a - m);
        den += w;
        acc += w * g_xw[(size_t)ad * HH + h];
    }
    float v = acc / (den + 1e-16f) + bias[h];
    v = fmaxf(v, 0.f);  // both RGAT layers are followed by ReLU
    Y[(size_t)n * HH + h] = v;
}

// ---------------- Wl transpose (final linear uses h @ Wl^T) ----------------
__global__ void transpose_kernel(const float* __restrict__ Wl) {
    int idx = blockIdx.x * blockDim.x + threadIdx.x;  // 16384
    if (idx < HH * HH) {
        int o = idx / HH, hc = idx % HH;
        g_wlt[hc * HH + o] = Wl[o * HH + hc];
    }
}

// ---------------- launch ----------------
extern "C" void kernel_launch(void* const* d_in, const int* in_sizes, int n_in,
                              void* d_out, int out_size)
{
    const float* x  = (const float*)d_in[0];
    const int*   ei = (const int*)d_in[1];
    const int*   et = (const int*)d_in[2];
    // d_in[3] = batch (unused: equal-size sorted graphs -> plain reshape)
    const float* W1 = (const float*)d_in[4];
    const float* q1 = (const float*)d_in[5];
    const float* k1 = (const float*)d_in[6];
    const float* b1 = (const float*)d_in[7];
    const float* W2 = (const float*)d_in[8];
    const float* q2 = (const float*)d_in[9];
    const float* k2 = (const float*)d_in[10];
    const float* b2 = (const float*)d_in[11];
    const float* Wl = (const float*)d_in[12];
    const float* bl = (const float*)d_in[13];
    const int* src = ei;
    const int* tgt = ei + EE;

    float *p_xw, *p_h1, *p_h2, *p_wlt, *p_pq, *p_pk;
    cudaGetSymbolAddress((void**)&p_xw, g_xw);
    cudaGetSymbolAddress((void**)&p_h1, g_h1);
    cudaGetSymbolAddress((void**)&p_h2, g_h2);
    cudaGetSymbolAddress((void**)&p_wlt, g_wlt);
    cudaGetSymbolAddress((void**)&p_pq, g_pq);
    cudaGetSymbolAddress((void**)&p_pk, g_pk);

    const int SMEM_BYTES = 2 * 2560 * 16;  // 81920
    cudaFuncSetAttribute(gemm_mma, cudaFuncAttributeMaxDynamicSharedMemorySize, SMEM_BYTES);

    const int EB = (EE + 255) / 256;
    const int NB = (NN + 255) / 256;
    const int SQB = (NN + 3) / 4;

    // ---- launches #1-#3, then gemm at #4 (the slot ncu profiles) ----
    prep_a_kernel<<<MBLK, 128>>>(x, NN);                        // 1
    prep_b_kernel<<<RR * 4, 128>>>(W1);                         // 2
    zero_counts_kernel<<<NB, 256>>>();                          // 3
    gemm_mma<<<dim3(MBLK, RR), 128, SMEM_BYTES>>>(p_xw, NN, nullptr);  // 4 <- ncu slot

    // CSR build (shared by both layers)
    hist_kernel<<<EB, 256>>>(tgt);                              // 5
    scan_kernel<<<1, 1024>>>();                                 // 6
    copy_cursor_kernel<<<NB, 256>>>();                          // 7
    scatter_kernel<<<EB, 256>>>(src, tgt, et);                  // 8
    transpose_kernel<<<(HH * HH + 255) / 256, 256>>>(Wl);       // 9

    // ---- layer 1 attention ----
    proj_kernel<<<128, 256>>>(W1, q1, k1, p_pq, p_pk);
    sqsk_kernel<<<SQB, 128>>>(x);
    minit_kernel<<<NB, 256>>>();
    alpha_kernel<<<EB, 256>>>(src, tgt, et);
    agg_kernel<<<NN, HH>>>(b1, p_h1);

    // ---- layer 2 ----
    prep_a_kernel<<<MBLK, 128>>>(p_h1, NN);
    prep_b_kernel<<<RR * 4, 128>>>(W2);
    gemm_mma<<<dim3(MBLK, RR), 128, SMEM_BYTES>>>(p_xw, NN, nullptr);
    proj_kernel<<<128, 256>>>(W2, q2, k2, p_pq, p_pk);
    sqsk_kernel<<<SQB, 128>>>(p_h1);
    minit_kernel<<<NB, 256>>>();
    alpha_kernel<<<EB, 256>>>(src, tgt, et);
    agg_kernel<<<NN, HH>>>(b2, p_h2);

    // ---- final linear straight into d_out ([B,NPG,H] is contiguous [N,H]) ----
    prep_a_kernel<<<MBLK, 128>>>(p_h2, NN);
    prep_b_kernel<<<4, 128>>>(p_wlt);
    gemm_mma<<<dim3(MBLK, 1), 128, SMEM_BYTES>>>((float*)d_out, NN, bl);
}

// round 15
// speedup vs baseline: 2.3774x; 1.0687x over previous
#include <cuda_runtime.h>
#include <cuda_bf16.h>

#define NN 50000
#define EE 800000
#define RR 8
#define HH 128
#define MBLK 391   // ceil(NN/128)
#define MAXDEG 128

// ---------------- scratch (device globals; no allocation allowed) ----------------
__device__ float    g_xw[(size_t)RR * NN * HH];   // per-relation transformed features
__device__ float    g_sq[RR * NN];
__device__ float    g_sk[RR * NN];
__device__ float    g_h1[(size_t)NN * HH];
__device__ float    g_h2[(size_t)NN * HH];
__device__ int      g_counts[NN];
__device__ int      g_off[NN + 1];
__device__ int      g_cursor[NN];
__device__ int      g_rsrc[EE];                   // slot -> r*NN+src
__device__ float    g_wlt[HH * HH];
__device__ float    g_pq[RR * HH];
__device__ float    g_pk[RR * HH];
__device__ float4   g_asp[(size_t)MBLK * 4 * 2048];  // pre-split A, smem slot layout
__device__ float4   g_bsp[RR * 4 * 2048];            // pre-split B

// ---------------- helpers ----------------
__device__ __forceinline__ float tf32_rna(float x) {
    unsigned r;
    asm("cvt.rna.tf32.f32 %0, %1;" : "=r"(r) : "f"(x));
    return __uint_as_float(r);
}
__device__ __forceinline__ void tf32_split(float x, float& hi, float& lo) {
    hi = tf32_rna(x);
    lo = tf32_rna(x - hi);
}

#define MMA_TF32(C, A0, A1, A2, A3, B0, B1)                                         \
    asm volatile("mma.sync.aligned.m16n8k8.row.col.f32.tf32.tf32.f32 "             \
                 "{%0,%1,%2,%3}, {%4,%5,%6,%7}, {%8,%9}, {%0,%1,%2,%3};"           \
                 : "+f"((C)[0]), "+f"((C)[1]), "+f"((C)[2]), "+f"((C)[3])          \
                 : "r"(A0), "r"(A1), "r"(A2), "r"(A3), "r"(B0), "r"(B1))

// ---------------- prep A: split into gemm smem slot layout, tiled by 128-row block ------
// layout: g_asp[(blk*4+kc)*2048 + (ks*128 + row)*4 + slot]
// slot c = {hi(k=c), hi(k=c+4), lo(k=c), lo(k=c+4)} within k-step ks
__global__ void prep_a_kernel(const float* __restrict__ A, int M)
{
    const int tid = threadIdx.x;
    const int blk = blockIdx.x;
    const int grow = blk * 128 + tid;
    const float4 z4 = make_float4(0.f, 0.f, 0.f, 0.f);
    const float4* ap = reinterpret_cast<const float4*>(A + (size_t)grow * HH);
#pragma unroll
    for (int kc = 0; kc < 4; kc++) {
        float4* dst = g_asp + ((size_t)(blk * 4 + kc)) * 2048;
#pragma unroll
        for (int ks = 0; ks < 4; ks++) {
            float4 u = z4, v = z4;
            if (grow < M) { u = ap[kc * 8 + ks * 2]; v = ap[kc * 8 + ks * 2 + 1]; }
            float uh[4], ul[4], vh[4], vl[4];
            tf32_split(u.x, uh[0], ul[0]); tf32_split(u.y, uh[1], ul[1]);
            tf32_split(u.z, uh[2], ul[2]); tf32_split(u.w, uh[3], ul[3]);
            tf32_split(v.x, vh[0], vl[0]); tf32_split(v.y, vh[1], vl[1]);
            tf32_split(v.z, vh[2], vl[2]); tf32_split(v.w, vh[3], vl[3]);
#pragma unroll
            for (int c = 0; c < 4; c++)
                dst[(ks * 128 + tid) * 4 + c] = make_float4(uh[c], vh[c], ul[c], vl[c]);
        }
    }
}

// ---------------- prep B: same slot layout per (r, kc); blockIdx.x = r*4+kc ----------
__global__ void prep_b_kernel(const float* __restrict__ Bmat)
{
    const int r = blockIdx.x >> 2;
    const int kc = blockIdx.x & 3;
    const int n = threadIdx.x;
    float4* dst = g_bsp + (size_t)blockIdx.x * 2048;
#pragma unroll
    for (int ks = 0; ks < 4; ks++) {
        float e[8];
#pragma unroll
        for (int kk = 0; kk < 8; kk++)
            e[kk] = Bmat[(size_t)r * HH * HH + (size_t)(kc * 32 + ks * 8 + kk) * HH + n];
#pragma unroll
        for (int c = 0; c < 4; c++) {
            float h0, l0, h1, l1;
            tf32_split(e[c], h0, l0);
            tf32_split(e[c + 4], h1, l1);
            dst[(ks * 128 + n) * 4 + c] = make_float4(h0, h1, l0, l1);
        }
    }
}

// ---------------- 3xTF32 mma GEMM on pre-split operands ----------------
// Block tile 128x128, K-chunk 32 (4 k-steps of 8), 256 threads = 8 warps (2m x 4n).
// Warp tile 64x32: 4 m16-tiles x 4 n8-tiles -> acc = 64 regs.
__global__ void __launch_bounds__(256, 2)
gemm_mma(float* __restrict__ C, int M, const float* __restrict__ bias)
{
    extern __shared__ float4 sm4[];
    float4* As4 = sm4;                  // 2560 float4
    float4* Bs4 = sm4 + 2560;

    const int r = blockIdx.y;
    float* Cr = C + (size_t)r * M * HH;
    const int row0 = blockIdx.x * 128;
    const int tid = threadIdx.x;
    const int lane = tid & 31;
    const int wid = tid >> 5;
    const int warp_m = (wid & 1) << 6;   // 0 or 64
    const int warp_n = (wid >> 1) << 5;  // 0,32,64,96
    const int g  = lane >> 2;            // 0..7
    const int cq = lane & 3;             // 0..3

    float acc[4][4][4];
#pragma unroll
    for (int mt = 0; mt < 4; mt++)
#pragma unroll
        for (int nt = 0; nt < 4; nt++)
#pragma unroll
            for (int j = 0; j < 4; j++) acc[mt][nt][j] = 0.f;

#pragma unroll 1
    for (int kc = 0; kc < 4; kc++) {
        const float4* asrc = g_asp + ((size_t)(blockIdx.x * 4 + kc)) * 2048;
        const float4* bsrc = g_bsp + ((size_t)(r * 4 + kc)) * 2048;
#pragma unroll
        for (int it = 0; it < 8; it++) {
            int idx = tid + it * 256;
            int d = (idx >> 2) * 5 + (idx & 3);
            As4[d] = asrc[idx];
            Bs4[d] = bsrc[idx];
        }
        __syncthreads();

#pragma unroll
        for (int ks = 0; ks < 4; ks++) {
            unsigned bh[4][2], bl[4][2];
#pragma unroll
            for (int nt = 0; nt < 4; nt++) {
                float4 w = Bs4[(ks * 128 + warp_n + nt * 8 + g) * 5 + cq];
                bh[nt][0] = __float_as_uint(w.x); bh[nt][1] = __float_as_uint(w.y);
                bl[nt][0] = __float_as_uint(w.z); bl[nt][1] = __float_as_uint(w.w);
            }
#pragma unroll
            for (int mt = 0; mt < 4; mt++) {
                float4 v1 = As4[(ks * 128 + warp_m + mt * 16 + g) * 5 + cq];
                float4 v2 = As4[(ks * 128 + warp_m + mt * 16 + 8 + g) * 5 + cq];
                unsigned ah0 = __float_as_uint(v1.x), ah1 = __float_as_uint(v2.x);
                unsigned ah2 = __float_as_uint(v1.y), ah3 = __float_as_uint(v2.y);
                unsigned al0 = __float_as_uint(v1.z), al1 = __float_as_uint(v2.z);
                unsigned al2 = __float_as_uint(v1.w), al3 = __float_as_uint(v2.w);
#pragma unroll
                for (int nt = 0; nt < 4; nt++)
                    MMA_TF32(acc[mt][nt], ah0, ah1, ah2, ah3, bh[nt][0], bh[nt][1]);
#pragma unroll
                for (int nt = 0; nt < 4; nt++)
                    MMA_TF32(acc[mt][nt], ah0, ah1, ah2, ah3, bl[nt][0], bl[nt][1]);
#pragma unroll
                for (int nt = 0; nt < 4; nt++)
                    MMA_TF32(acc[mt][nt], al0, al1, al2, al3, bh[nt][0], bh[nt][1]);
            }
        }
        __syncthreads();
    }

    // ---- epilogue ----
#pragma unroll
    for (int mt = 0; mt < 4; mt++) {
        int r_lo = row0 + warp_m + mt * 16 + g;
        int r_hi = r_lo + 8;
#pragma unroll
        for (int nt = 0; nt < 4; nt++) {
            int col = warp_n + nt * 8 + 2 * cq;
            float b0v = 0.f, b1v = 0.f;
            if (bias) { b0v = bias[col]; b1v = bias[col + 1]; }
            if (r_lo < M) {
                float2* p = reinterpret_cast<float2*>(Cr + (size_t)r_lo * HH + col);
                *p = make_float2(acc[mt][nt][0] + b0v, acc[mt][nt][1] + b1v);
            }
            if (r_hi < M) {
                float2* p = reinterpret_cast<float2*>(Cr + (size_t)r_hi * HH + col);
                *p = make_float2(acc[mt][nt][2] + b0v, acc[mt][nt][3] + b1v);
            }
        }
    }
}

// ---------------- attention projection vectors: P[r] = W[r] @ q (and @ k) ----------------
__global__ void proj_kernel(const float* __restrict__ W, const float* __restrict__ qv,
                            const float* __restrict__ kv,
                            float* __restrict__ Pq, float* __restrict__ Pk)
{
    int warp = (blockIdx.x * blockDim.x + threadIdx.x) >> 5;
    int lane = threadIdx.x & 31;
    int r = warp >> 7, i = warp & 127;
    const float* wrow = W + ((size_t)r * HH + i) * HH;
    float aq = 0.f, ak = 0.f;
#pragma unroll
    for (int o = 0; o < 4; o++) {
        float w = wrow[lane + o * 32];
        aq += w * qv[lane + o * 32];
        ak += w * kv[lane + o * 32];
    }
#pragma unroll
    for (int off = 16; off > 0; off >>= 1) {
        aq += __shfl_down_sync(0xffffffffu, aq, off);
        ak += __shfl_down_sync(0xffffffffu, ak, off);
    }
    if (lane == 0) { Pq[r * HH + i] = aq; Pk[r * HH + i] = ak; }
}

// ---------------- sq[r][n] = X[n] . Pq[r] ; sk likewise (exact fp32) ----------------
__global__ void sqsk_kernel(const float* __restrict__ X)
{
    __shared__ float sPq[RR * HH], sPk[RR * HH];
    for (int i = threadIdx.x; i < RR * HH; i += 128) {
        sPq[i] = g_pq[i];
        sPk[i] = g_pk[i];
    }
    __syncthreads();
    int n = blockIdx.x * 4 + (threadIdx.x >> 5);
    if (n >= NN) return;
    int lane = threadIdx.x & 31;
    float x0 = X[(size_t)n * HH + lane];
    float x1 = X[(size_t)n * HH + lane + 32];
    float x2 = X[(size_t)n * HH + lane + 64];
    float x3 = X[(size_t)n * HH + lane + 96];
#pragma unroll
    for (int r = 0; r < RR; r++) {
        const float* pq = &sPq[r * HH];
        const float* pk = &sPk[r * HH];
        float aq = x0 * pq[lane] + x1 * pq[lane + 32] + x2 * pq[lane + 64] + x3 * pq[lane + 96];
        float ak = x0 * pk[lane] + x1 * pk[lane + 32] + x2 * pk[lane + 64] + x3 * pk[lane + 96];
#pragma unroll
        for (int off = 16; off > 0; off >>= 1) {
            aq += __shfl_down_sync(0xffffffffu, aq, off);
            ak += __shfl_down_sync(0xffffffffu, ak, off);
        }
        if (lane == 0) { g_sq[r * NN + n] = aq; g_sk[r * NN + n] = ak; }
    }
}

// ---------------- CSR build (tgt is identical across both layers) ----------------
__global__ void zero_counts_kernel() {
    int n = blockIdx.x * blockDim.x + threadIdx.x;
    if (n < NN) g_counts[n] = 0;
}
__global__ void hist_kernel(const int* __restrict__ tgt) {
    int e = blockIdx.x * blockDim.x + threadIdx.x;
    if (e < EE) atomicAdd(&g_counts[tgt[e]], 1);
}
__global__ void scan_kernel() {
    __shared__ int part[1024];
    const int tid = threadIdx.x;
    const int CH = (NN + 1023) / 1024;
    const int st = tid * CH;
    int s = 0;
    for (int i = 0; i < CH; i++) {
        int idx = st + i;
        if (idx < NN) s += g_counts[idx];
    }
    part[tid] = s;
    __syncthreads();
    for (int off = 1; off < 1024; off <<= 1) {
        int add = (tid >= off) ? part[tid - off] : 0;
        __syncthreads();
        part[tid] += add;
        __syncthreads();
    }
    int run = (tid == 0) ? 0 : part[tid - 1];
    for (int i = 0; i < CH; i++) {
        int idx = st + i;
        if (idx < NN) {
            g_off[idx] = run;
            run += g_counts[idx];
        }
    }
    if (tid == 1023) g_off[NN] = part[1023];
}
__global__ void copy_cursor_kernel() {
    int n = blockIdx.x * blockDim.x + threadIdx.x;
    if (n < NN) g_cursor[n] = g_off[n];
}
__global__ void scatter_kernel(const int* __restrict__ src, const int* __restrict__ tgt,
                               const int* __restrict__ et) {
    int e = blockIdx.x * blockDim.x + threadIdx.x;
    if (e < EE) {
        int pos = atomicAdd(&g_cursor[tgt[e]], 1);
        g_rsrc[pos] = et[e] * NN + src[e];
    }
}

// ---------------- fused alpha + softmax + weighted aggregation ----------------
// warp-per-node; 256 threads = 8 warps/block; grid = NN/8 (exact).
// alpha_e = sq[r][tgt] + sk[r][src] computed inline (sq via lane shfl broadcast;
// sk and feature row share the packed index ad = r*NN+src).
__global__ void __launch_bounds__(256)
agg_fused(const float* __restrict__ bias, float* __restrict__ Y)
{
    __shared__ float sw[8][MAXDEG];
    const int w = threadIdx.x >> 5;
    const int lane = threadIdx.x & 31;
    const int n = blockIdx.x * 8 + w;
    const int beg = g_off[n], end = g_off[n + 1];
    const int deg = end - beg;
    const int nb = (deg + 31) >> 5;

    // sq values for this node, all 8 relations (lane r holds sq[r][n])
    float sqv = (lane < RR) ? g_sq[lane * NN + n] : 0.f;

    // ---- pass 1: alpha + warp max ----
    float areg[4];
    float mx = -1e30f;
    for (int b = 0; b < nb; b++) {
        int i = (b << 5) + lane;
        bool act = i < deg;
        int ad = g_rsrc[act ? beg + i : beg];
        int rr = ad / NN;
        float a = __shfl_sync(0xffffffffu, sqv, rr) + g_sk[ad];
        a = (a > 0.f) ? a : 0.2f * a;
        if (b < 4) areg[b] = a;
        if (act) mx = fmaxf(mx, a);
    }
#pragma unroll
    for (int off = 16; off > 0; off >>= 1)
        mx = fmaxf(mx, __shfl_xor_sync(0xffffffffu, mx, off));

    // ---- pass 2: exp + den; stash weights in smem for cross-lane reuse ----
    float den = 0.f;
    for (int b = 0; b < nb; b++) {
        int i = (b << 5) + lane;
        bool act = i < deg;
        float a;
        if (b < 4) {
            a = areg[b];
        } else {
            int ad = g_rsrc[act ? beg + i : beg];
            int rr = ad / NN;
            a = __shfl_sync(0xffffffffu, sqv, rr) + g_sk[ad];
            a = (a > 0.f) ? a : 0.2f * a;
        }
        float ex = act ? __expf(a - mx) : 0.f;
        den += ex;
        if (act && i < MAXDEG) sw[w][i] = ex;
    }
#pragma unroll
    for (int off = 16; off > 0; off >>= 1)
        den += __shfl_xor_sync(0xffffffffu, den, off);
    __syncwarp();

    // ---- pass 3: weighted aggregation, float4 per lane ----
    float4 acc = make_float4(0.f, 0.f, 0.f, 0.f);
    for (int j = 0; j < deg; j++) {
        int ad = g_rsrc[beg + j];              // uniform -> broadcast load
        float wj;
        if (j < MAXDEG) {
            wj = sw[w][j];
        } else {
            int rr = ad / NN;
            float a = __shfl_sync(0xffffffffu, sqv, rr) + g_sk[ad];
            a = (a > 0.f) ? a : 0.2f * a;
            wj = __expf(a - mx);
        }
        float4 f = reinterpret_cast<const float4*>(g_xw + (size_t)ad * HH)[lane];
        acc.x += wj * f.x; acc.y += wj * f.y;
        acc.z += wj * f.z; acc.w += wj * f.w;
    }
    float inv = 1.f / (den + 1e-16f);
    float4 bv = reinterpret_cast<const float4*>(bias)[lane];
    float4 out;
    out.x = fmaxf(acc.x * inv + bv.x, 0.f);
    out.y = fmaxf(acc.y * inv + bv.y, 0.f);
    out.z = fmaxf(acc.z * inv + bv.z, 0.f);
    out.w = fmaxf(acc.w * inv + bv.w, 0.f);
    reinterpret_cast<float4*>(Y + (size_t)n * HH)[lane] = out;
}

// ---------------- Wl transpose (final linear uses h @ Wl^T) ----------------
__global__ void transpose_kernel(const float* __restrict__ Wl) {
    int idx = blockIdx.x * blockDim.x + threadIdx.x;  // 16384
    if (idx < HH * HH) {
        int o = idx / HH, hc = idx % HH;
        g_wlt[hc * HH + o] = Wl[o * HH + hc];
    }
}

// ---------------- launch ----------------
extern "C" void kernel_launch(void* const* d_in, const int* in_sizes, int n_in,
                              void* d_out, int out_size)
{
    const float* x  = (const float*)d_in[0];
    const int*   ei = (const int*)d_in[1];
    const int*   et = (const int*)d_in[2];
    // d_in[3] = batch (unused: equal-size sorted graphs -> plain reshape)
    const float* W1 = (const float*)d_in[4];
    const float* q1 = (const float*)d_in[5];
    const float* k1 = (const float*)d_in[6];
    const float* b1 = (const float*)d_in[7];
    const float* W2 = (const float*)d_in[8];
    const float* q2 = (const float*)d_in[9];
    const float* k2 = (const float*)d_in[10];
    const float* b2 = (const float*)d_in[11];
    const float* Wl = (const float*)d_in[12];
    const float* bl = (const float*)d_in[13];
    const int* src = ei;
    const int* tgt = ei + EE;

    float *p_xw, *p_h1, *p_h2, *p_wlt, *p_pq, *p_pk;
    cudaGetSymbolAddress((void**)&p_xw, g_xw);
    cudaGetSymbolAddress((void**)&p_h1, g_h1);
    cudaGetSymbolAddress((void**)&p_h2, g_h2);
    cudaGetSymbolAddress((void**)&p_wlt, g_wlt);
    cudaGetSymbolAddress((void**)&p_pq, g_pq);
    cudaGetSymbolAddress((void**)&p_pk, g_pk);

    const int SMEM_BYTES = 2 * 2560 * 16;  // 81920
    cudaFuncSetAttribute(gemm_mma, cudaFuncAttributeMaxDynamicSharedMemorySize, SMEM_BYTES);

    const int EB = (EE + 255) / 256;
    const int NB = (NN + 255) / 256;
    const int SQB = (NN + 3) / 4;
    const int AGB = NN / 8;  // 6250, exact

    // ---- launches #1-#3, then gemm at #4 (the slot ncu profiles) ----
    prep_a_kernel<<<MBLK, 128>>>(x, NN);                        // 1
    prep_b_kernel<<<RR * 4, 128>>>(W1);                         // 2
    zero_counts_kernel<<<NB, 256>>>();                          // 3
    gemm_mma<<<dim3(MBLK, RR), 256, SMEM_BYTES>>>(p_xw, NN, nullptr);  // 4 <- ncu slot

    // CSR build (shared by both layers)
    hist_kernel<<<EB, 256>>>(tgt);
    scan_kernel<<<1, 1024>>>();
    copy_cursor_kernel<<<NB, 256>>>();
    scatter_kernel<<<EB, 256>>>(src, tgt, et);
    transpose_kernel<<<(HH * HH + 255) / 256, 256>>>(Wl);

    // ---- layer 1 attention ----
    proj_kernel<<<128, 256>>>(W1, q1, k1, p_pq, p_pk);
    sqsk_kernel<<<SQB, 128>>>(x);
    agg_fused<<<AGB, 256>>>(b1, p_h1);

    // ---- layer 2 ----
    prep_a_kernel<<<MBLK, 128>>>(p_h1, NN);
    prep_b_kernel<<<RR * 4, 128>>>(W2);
    gemm_mma<<<dim3(MBLK, RR), 256, SMEM_BYTES>>>(p_xw, NN, nullptr);
    proj_kernel<<<128, 256>>>(W2, q2, k2, p_pq, p_pk);
    sqsk_kernel<<<SQB, 128>>>(p_h1);
    agg_fused<<<AGB, 256>>>(b2, p_h2);

    // ---- final linear straight into d_out ([B,NPG,H] is contiguous [N,H]) ----
    prep_a_kernel<<<MBLK, 128>>>(p_h2, NN);
    prep_b_kernel<<<4, 128>>>(p_wlt);
    gemm_mma<<<dim3(MBLK, 1), 256, SMEM_BYTES>>>((float*)d_out, NN, bl);
}

// round 16
// speedup vs baseline: 3.4879x; 1.4671x over previous
#include <cuda_runtime.h>
#include <cuda_bf16.h>

#define NN 50000
#define EE 800000
#define RR 8
#define HH 128
#define MBLK 391   // ceil(NN/128)
#define MAXDEG 128

// ---------------- scratch (device globals; no allocation allowed) ----------------
__device__ float    g_xw[(size_t)RR * NN * HH];
__device__ float    g_sq[RR * NN];
__device__ float    g_sk[RR * NN];
__device__ float    g_h1[(size_t)NN * HH];
__device__ float    g_h2[(size_t)NN * HH];
__device__ int      g_counts[NN];
__device__ int      g_off[NN + 1];
__device__ int      g_cursor[NN];
__device__ int      g_rsrc[EE];                   // slot -> r*NN+src
__device__ float    g_wlt[HH * HH];
__device__ float    g_pq[RR * HH];
__device__ float    g_pk[RR * HH];
// pre-split bf16 fragments, register layout:
// [blk][kc:4][ks:2][tile:8][part:2(hi,lo)][lane:32] uint4
__device__ uint4    g_asp[(size_t)MBLK * 4096];
__device__ uint4    g_bsp[RR * 4096];

// ---------------- helpers ----------------
__device__ __forceinline__ unsigned pack2bf(float lo, float hi) {
    unsigned r;
    asm("cvt.rn.bf16x2.f32 %0, %1, %2;" : "=r"(r) : "f"(hi), "f"(lo));
    return r;
}
__device__ __forceinline__ void bf16_split(float x, float& h, float& l) {
    h = __bfloat162float(__float2bfloat16_rn(x));
    l = x - h;
}

#define MMA_BF16(C, A0, A1, A2, A3, B0, B1)                                         \
    asm volatile("mma.sync.aligned.m16n8k16.row.col.f32.bf16.bf16.f32 "            \
                 "{%0,%1,%2,%3}, {%4,%5,%6,%7}, {%8,%9}, {%0,%1,%2,%3};"           \
                 : "+f"((C)[0]), "+f"((C)[1]), "+f"((C)[2]), "+f"((C)[3])          \
                 : "r"(A0), "r"(A1), "r"(A2), "r"(A3), "r"(B0), "r"(B1))

// ---------------- prep A: bf16 hi/lo fragment layout ----------------
// fragment (m16n8k16 A, row-major): lane(g,cq), tile mi rows mi*16+g, mi*16+8+g;
// a0={A[g][2cq],A[g][2cq+1]} a1=rows+8 a2={A[g][2cq+8],A[g][2cq+9]} a3=rows+8.
__global__ void prep_a_kernel(const float* __restrict__ A, int M)
{
    const int t = threadIdx.x;
    const int blk = blockIdx.x;
    const int lane = t & 31;
    const int g = lane >> 2, cq = lane & 3;
    const int miq = t >> 5;  // 0..3
#pragma unroll
    for (int kc = 0; kc < 4; kc++)
#pragma unroll
        for (int ks = 0; ks < 2; ks++)
#pragma unroll
            for (int mm = 0; mm < 2; mm++) {
                const int mi = miq + mm * 4;
                const int r0 = blk * 128 + mi * 16 + g;
                const int r1 = r0 + 8;
                const int c = kc * 32 + ks * 16 + 2 * cq;
                float f[2][4];
#pragma unroll
                for (int rr = 0; rr < 2; rr++) {
                    int gr = rr ? r1 : r0;
                    if (gr < M) {
                        const float* ap = A + (size_t)gr * HH + c;
                        f[rr][0] = ap[0]; f[rr][1] = ap[1];
                        f[rr][2] = ap[8]; f[rr][3] = ap[9];
                    } else {
                        f[rr][0] = f[rr][1] = f[rr][2] = f[rr][3] = 0.f;
                    }
                }
                float h[2][4], l[2][4];
#pragma unroll
                for (int rr = 0; rr < 2; rr++)
#pragma unroll
                    for (int j = 0; j < 4; j++) bf16_split(f[rr][j], h[rr][j], l[rr][j]);
                uint4 Hi, Lo;
                Hi.x = pack2bf(h[0][0], h[0][1]); Hi.y = pack2bf(h[1][0], h[1][1]);
                Hi.z = pack2bf(h[0][2], h[0][3]); Hi.w = pack2bf(h[1][2], h[1][3]);
                Lo.x = pack2bf(l[0][0], l[0][1]); Lo.y = pack2bf(l[1][0], l[1][1]);
                Lo.z = pack2bf(l[0][2], l[0][3]); Lo.w = pack2bf(l[1][2], l[1][3]);
                size_t base = (size_t)blk * 4096 + (size_t)(((kc * 2 + ks) * 8 + mi) * 2) * 32 + lane;
                g_asp[base] = Hi;
                g_asp[base + 32] = Lo;
            }
}

// ---------------- prep B: bf16 hi/lo fragment layout; blockIdx = r ----------------
// fragment (m16n8k16 B, col-major): lane(g,cq): b0={B[2cq][n],B[2cq+1][n]},
// b1={B[2cq+8][n],B[2cq+9][n]}, n = tile*8+g. npair packs tiles 2np,2np+1.
__global__ void prep_b_kernel(const float* __restrict__ Bmat)
{
    const int r = blockIdx.x;
    const int t = threadIdx.x;
    const int lane = t & 31;
    const int g = lane >> 2, cq = lane & 3;
    const int npq = t >> 5;  // 0..3
    const float* B = Bmat + (size_t)r * HH * HH;
#pragma unroll
    for (int kc = 0; kc < 4; kc++)
#pragma unroll
        for (int ks = 0; ks < 2; ks++)
#pragma unroll
            for (int nm = 0; nm < 2; nm++) {
                const int np = npq + nm * 4;
                const int n0 = 16 * np + g;
                const int n1 = n0 + 8;
                const int c = kc * 32 + ks * 16 + 2 * cq;
                float f[2][4];  // [n][k-pos: 2cq,2cq+1,2cq+8,2cq+9]
#pragma unroll
                for (int nn = 0; nn < 2; nn++) {
                    int col = nn ? n1 : n0;
                    f[nn][0] = B[(size_t)(c) * HH + col];
                    f[nn][1] = B[(size_t)(c + 1) * HH + col];
                    f[nn][2] = B[(size_t)(c + 8) * HH + col];
                    f[nn][3] = B[(size_t)(c + 9) * HH + col];
                }
                float h[2][4], l[2][4];
#pragma unroll
                for (int nn = 0; nn < 2; nn++)
#pragma unroll
                    for (int j = 0; j < 4; j++) bf16_split(f[nn][j], h[nn][j], l[nn][j]);
                uint4 Hi, Lo;
                Hi.x = pack2bf(h[0][0], h[0][1]); Hi.y = pack2bf(h[0][2], h[0][3]);
                Hi.z = pack2bf(h[1][0], h[1][1]); Hi.w = pack2bf(h[1][2], h[1][3]);
                Lo.x = pack2bf(l[0][0], l[0][1]); Lo.y = pack2bf(l[0][2], l[0][3]);
                Lo.z = pack2bf(l[1][0], l[1][1]); Lo.w = pack2bf(l[1][2], l[1][3]);
                size_t base = (size_t)r * 4096 + (size_t)(((kc * 2 + ks) * 8 + np) * 2) * 32 + lane;
                g_bsp[base] = Hi;
                g_bsp[base + 32] = Lo;
            }
}

// ---------------- 3xBF16 mma GEMM on pre-split fragments ----------------
// Block tile 128x128, K-chunk 32 (2 ksteps of 16), 256 threads = 8 warps (2m x 4n).
// Warp tile 64x32: 4 m16-tiles x 4 n8-tiles. acc = 64 regs.
__global__ void __launch_bounds__(256, 2)
gemm_mma(float* __restrict__ C, int M, const float* __restrict__ bias)
{
    extern __shared__ uint4 smu[];
    uint4* As = smu;          // 1024 uint4 per kchunk
    uint4* Bs = smu + 1024;

    const int r = blockIdx.y;
    float* Cr = C + (size_t)r * M * HH;
    const int row0 = blockIdx.x * 128;
    const int tid = threadIdx.x;
    const int lane = tid & 31;
    const int wid = tid >> 5;
    const int warp_m = (wid & 1) << 6;    // 0 or 64
    const int warp_n = (wid >> 1) << 5;   // 0,32,64,96
    const int mi0 = warp_m >> 4;          // 0 or 4
    const int np0 = warp_n >> 4;          // 0,2,4,6
    const int g  = lane >> 2;
    const int cq = lane & 3;

    float acc[4][4][4];
#pragma unroll
    for (int mt = 0; mt < 4; mt++)
#pragma unroll
        for (int nt = 0; nt < 4; nt++)
#pragma unroll
            for (int j = 0; j < 4; j++) acc[mt][nt][j] = 0.f;

#pragma unroll 1
    for (int kc = 0; kc < 4; kc++) {
        const uint4* asrc = g_asp + (size_t)blockIdx.x * 4096 + kc * 1024;
        const uint4* bsrc = g_bsp + (size_t)r * 4096 + kc * 1024;
#pragma unroll
        for (int it = 0; it < 4; it++) {
            int idx = tid + it * 256;
            As[idx] = asrc[idx];
            Bs[idx] = bsrc[idx];
        }
        __syncthreads();

#pragma unroll
        for (int ks = 0; ks < 2; ks++) {
            // B fragments: 2 npairs -> 4 n8 tiles, hi+lo
            unsigned bh[4][2], bl[4][2];
#pragma unroll
            for (int p = 0; p < 2; p++) {
                uint4 H = Bs[((ks * 8 + np0 + p) * 2) * 32 + lane];
                uint4 L = Bs[((ks * 8 + np0 + p) * 2 + 1) * 32 + lane];
                bh[2 * p][0] = H.x;     bh[2 * p][1] = H.y;
                bh[2 * p + 1][0] = H.z; bh[2 * p + 1][1] = H.w;
                bl[2 * p][0] = L.x;     bl[2 * p][1] = L.y;
                bl[2 * p + 1][0] = L.z; bl[2 * p + 1][1] = L.w;
            }
#pragma unroll
            for (int mt = 0; mt < 4; mt++) {
                uint4 Ah = As[((ks * 8 + mi0 + mt) * 2) * 32 + lane];
                uint4 Al = As[((ks * 8 + mi0 + mt) * 2 + 1) * 32 + lane];
#pragma unroll
                for (int nt = 0; nt < 4; nt++)
                    MMA_BF16(acc[mt][nt], Ah.x, Ah.y, Ah.z, Ah.w, bh[nt][0], bh[nt][1]);
#pragma unroll
                for (int nt = 0; nt < 4; nt++)
                    MMA_BF16(acc[mt][nt], Ah.x, Ah.y, Ah.z, Ah.w, bl[nt][0], bl[nt][1]);
#pragma unroll
                for (int nt = 0; nt < 4; nt++)
                    MMA_BF16(acc[mt][nt], Al.x, Al.y, Al.z, Al.w, bh[nt][0], bh[nt][1]);
            }
        }
        __syncthreads();
    }

    // ---- epilogue (D frag: d0,d1 = row g cols 2cq,2cq+1; d2,d3 = row g+8) ----
#pragma unroll
    for (int mt = 0; mt < 4; mt++) {
        int r_lo = row0 + warp_m + mt * 16 + g;
        int r_hi = r_lo + 8;
#pragma unroll
        for (int nt = 0; nt < 4; nt++) {
            int col = warp_n + nt * 8 + 2 * cq;
            float b0v = 0.f, b1v = 0.f;
            if (bias) { b0v = bias[col]; b1v = bias[col + 1]; }
            if (r_lo < M) {
                float2* p = reinterpret_cast<float2*>(Cr + (size_t)r_lo * HH + col);
                *p = make_float2(acc[mt][nt][0] + b0v, acc[mt][nt][1] + b1v);
            }
            if (r_hi < M) {
                float2* p = reinterpret_cast<float2*>(Cr + (size_t)r_hi * HH + col);
                *p = make_float2(acc[mt][nt][2] + b0v, acc[mt][nt][3] + b1v);
            }
        }
    }
}

// ---------------- attention projection vectors: P[r] = W[r] @ q (and @ k) ----------------
__global__ void proj_kernel(const float* __restrict__ W, const float* __restrict__ qv,
                            const float* __restrict__ kv,
                            float* __restrict__ Pq, float* __restrict__ Pk)
{
    int warp = (blockIdx.x * blockDim.x + threadIdx.x) >> 5;
    int lane = threadIdx.x & 31;
    int r = warp >> 7, i = warp & 127;
    const float* wrow = W + ((size_t)r * HH + i) * HH;
    float aq = 0.f, ak = 0.f;
#pragma unroll
    for (int o = 0; o < 4; o++) {
        float w = wrow[lane + o * 32];
        aq += w * qv[lane + o * 32];
        ak += w * kv[lane + o * 32];
    }
#pragma unroll
    for (int off = 16; off > 0; off >>= 1) {
        aq += __shfl_down_sync(0xffffffffu, aq, off);
        ak += __shfl_down_sync(0xffffffffu, ak, off);
    }
    if (lane == 0) { Pq[r * HH + i] = aq; Pk[r * HH + i] = ak; }
}

// ---------------- sq[r][n] = X[n] . Pq[r] ; sk likewise (exact fp32) ----------------
__global__ void sqsk_kernel(const float* __restrict__ X)
{
    __shared__ float sPq[RR * HH], sPk[RR * HH];
    for (int i = threadIdx.x; i < RR * HH; i += 128) {
        sPq[i] = g_pq[i];
        sPk[i] = g_pk[i];
    }
    __syncthreads();
    int n = blockIdx.x * 4 + (threadIdx.x >> 5);
    if (n >= NN) return;
    int lane = threadIdx.x & 31;
    float x0 = X[(size_t)n * HH + lane];
    float x1 = X[(size_t)n * HH + lane + 32];
    float x2 = X[(size_t)n * HH + lane + 64];
    float x3 = X[(size_t)n * HH + lane + 96];
#pragma unroll
    for (int r = 0; r < RR; r++) {
        const float* pq = &sPq[r * HH];
        const float* pk = &sPk[r * HH];
        float aq = x0 * pq[lane] + x1 * pq[lane + 32] + x2 * pq[lane + 64] + x3 * pq[lane + 96];
        float ak = x0 * pk[lane] + x1 * pk[lane + 32] + x2 * pk[lane + 64] + x3 * pk[lane + 96];
#pragma unroll
        for (int off = 16; off > 0; off >>= 1) {
            aq += __shfl_down_sync(0xffffffffu, aq, off);
            ak += __shfl_down_sync(0xffffffffu, ak, off);
        }
        if (lane == 0) { g_sq[r * NN + n] = aq; g_sk[r * NN + n] = ak; }
    }
}

// ---------------- CSR build (tgt is identical across both layers) ----------------
__global__ void zero_counts_kernel() {
    int n = blockIdx.x * blockDim.x + threadIdx.x;
    if (n < NN) g_counts[n] = 0;
}
__global__ void hist_kernel(const int* __restrict__ tgt) {
    int e = blockIdx.x * blockDim.x + threadIdx.x;
    if (e < EE) atomicAdd(&g_counts[tgt[e]], 1);
}
__global__ void scan_kernel() {
    __shared__ int part[1024];
    const int tid = threadIdx.x;
    const int CH = (NN + 1023) / 1024;
    const int st = tid * CH;
    int s = 0;
    for (int i = 0; i < CH; i++) {
        int idx = st + i;
        if (idx < NN) s += g_counts[idx];
    }
    part[tid] = s;
    __syncthreads();
    for (int off = 1; off < 1024; off <<= 1) {
        int add = (tid >= off) ? part[tid - off] : 0;
        __syncthreads();
        part[tid] += add;
        __syncthreads();
    }
    int run = (tid == 0) ? 0 : part[tid - 1];
    for (int i = 0; i < CH; i++) {
        int idx = st + i;
        if (idx < NN) {
            g_off[idx] = run;
            run += g_counts[idx];
        }
    }
    if (tid == 1023) g_off[NN] = part[1023];
}
__global__ void copy_cursor_kernel() {
    int n = blockIdx.x * blockDim.x + threadIdx.x;
    if (n < NN) g_cursor[n] = g_off[n];
}
__global__ void scatter_kernel(const int* __restrict__ src, const int* __restrict__ tgt,
                               const int* __restrict__ et) {
    int e = blockIdx.x * blockDim.x + threadIdx.x;
    if (e < EE) {
        int pos = atomicAdd(&g_cursor[tgt[e]], 1);
        g_rsrc[pos] = et[e] * NN + src[e];
    }
}

// ---------------- fused alpha + softmax + weighted aggregation ----------------
__global__ void __launch_bounds__(256)
agg_fused(const float* __restrict__ bias, float* __restrict__ Y)
{
    __shared__ float sw[8][MAXDEG];
    const int w = threadIdx.x >> 5;
    const int lane = threadIdx.x & 31;
    const int n = blockIdx.x * 8 + w;
    const int beg = g_off[n], end = g_off[n + 1];
    const int deg = end - beg;
    const int nb = (deg + 31) >> 5;

    float sqv = (lane < RR) ? g_sq[lane * NN + n] : 0.f;

    // ---- pass 1: alpha + warp max ----
    float areg[4];
    float mx = -1e30f;
    for (int b = 0; b < nb; b++) {
        int i = (b << 5) + lane;
        bool act = i < deg;
        int ad = g_rsrc[act ? beg + i : beg];
        int rr = ad / NN;
        float a = __shfl_sync(0xffffffffu, sqv, rr) + g_sk[ad];
        a = (a > 0.f) ? a : 0.2f * a;
        if (b < 4) areg[b] = a;
        if (act) mx = fmaxf(mx, a);
    }
#pragma unroll
    for (int off = 16; off > 0; off >>= 1)
        mx = fmaxf(mx, __shfl_xor_sync(0xffffffffu, mx, off));

    // ---- pass 2: exp + den ----
    float den = 0.f;
    for (int b = 0; b < nb; b++) {
        int i = (b << 5) + lane;
        bool act = i < deg;
        float a;
        if (b < 4) {
            a = areg[b];
        } else {
            int ad = g_rsrc[act ? beg + i : beg];
            int rr = ad / NN;
            a = __shfl_sync(0xffffffffu, sqv, rr) + g_sk[ad];
            a = (a > 0.f) ? a : 0.2f * a;
        }
        float ex = act ? __expf(a - mx) : 0.f;
        den += ex;
        if (act && i < MAXDEG) sw[w][i] = ex;
    }
#pragma unroll
    for (int off = 16; off > 0; off >>= 1)
        den += __shfl_xor_sync(0xffffffffu, den, off);
    __syncwarp();

    // ---- pass 3: weighted aggregation, float4 per lane ----
    float4 acc = make_float4(0.f, 0.f, 0.f, 0.f);
    for (int j = 0; j < deg; j++) {
        int ad = g_rsrc[beg + j];
        float wj;
        if (j < MAXDEG) {
            wj = sw[w][j];
        } else {
            int rr = ad / NN;
            float a = __shfl_sync(0xffffffffu, sqv, rr) + g_sk[ad];
            a = (a > 0.f) ? a : 0.2f * a;
            wj = __expf(a - mx);
        }
        float4 f = reinterpret_cast<const float4*>(g_xw + (size_t)ad * HH)[lane];
        acc.x += wj * f.x; acc.y += wj * f.y;
        acc.z += wj * f.z; acc.w += wj * f.w;
    }
    float inv = 1.f / (den + 1e-16f);
    float4 bv = reinterpret_cast<const float4*>(bias)[lane];
    float4 out;
    out.x = fmaxf(acc.x * inv + bv.x, 0.f);
    out.y = fmaxf(acc.y * inv + bv.y, 0.f);
    out.z = fmaxf(acc.z * inv + bv.z, 0.f);
    out.w = fmaxf(acc.w * inv + bv.w, 0.f);
    reinterpret_cast<float4*>(Y + (size_t)n * HH)[lane] = out;
}

// ---------------- Wl transpose (final linear uses h @ Wl^T) ----------------
__global__ void transpose_kernel(const float* __restrict__ Wl) {
    int idx = blockIdx.x * blockDim.x + threadIdx.x;
    if (idx < HH * HH) {
        int o = idx / HH, hc = idx % HH;
        g_wlt[hc * HH + o] = Wl[o * HH + hc];
    }
}

// ---------------- launch ----------------
extern "C" void kernel_launch(void* const* d_in, const int* in_sizes, int n_in,
                              void* d_out, int out_size)
{
    const float* x  = (const float*)d_in[0];
    const int*   ei = (const int*)d_in[1];
    const int*   et = (const int*)d_in[2];
    const float* W1 = (const float*)d_in[4];
    const float* q1 = (const float*)d_in[5];
    const float* k1 = (const float*)d_in[6];
    const float* b1 = (const float*)d_in[7];
    const float* W2 = (const float*)d_in[8];
    const float* q2 = (const float*)d_in[9];
    const float* k2 = (const float*)d_in[10];
    const float* b2 = (const float*)d_in[11];
    const float* Wl = (const float*)d_in[12];
    const float* bl = (const float*)d_in[13];
    const int* src = ei;
    const int* tgt = ei + EE;

    float *p_xw, *p_h1, *p_h2, *p_wlt, *p_pq, *p_pk;
    cudaGetSymbolAddress((void**)&p_xw, g_xw);
    cudaGetSymbolAddress((void**)&p_h1, g_h1);
    cudaGetSymbolAddress((void**)&p_h2, g_h2);
    cudaGetSymbolAddress((void**)&p_wlt, g_wlt);
    cudaGetSymbolAddress((void**)&p_pq, g_pq);
    cudaGetSymbolAddress((void**)&p_pk, g_pk);

    const int SMEM_BYTES = 2048 * 16;  // 32KB
    cudaFuncSetAttribute(gemm_mma, cudaFuncAttributeMaxDynamicSharedMemorySize, SMEM_BYTES);

    const int EB = (EE + 255) / 256;
    const int NB = (NN + 255) / 256;
    const int SQB = (NN + 3) / 4;
    const int AGB = NN / 8;

    // ---- launches #1-#3, then gemm at #4 (the slot ncu profiles) ----
    prep_a_kernel<<<MBLK, 128>>>(x, NN);                        // 1
    prep_b_kernel<<<RR, 128>>>(W1);                             // 2
    zero_counts_kernel<<<NB, 256>>>();                          // 3
    gemm_mma<<<dim3(MBLK, RR), 256, SMEM_BYTES>>>(p_xw, NN, nullptr);  // 4 <- ncu slot

    // CSR build (shared by both layers)
    hist_kernel<<<EB, 256>>>(tgt);
    scan_kernel<<<1, 1024>>>();
    copy_cursor_kernel<<<NB, 256>>>();
    scatter_kernel<<<EB, 256>>>(src, tgt, et);
    transpose_kernel<<<(HH * HH + 255) / 256, 256>>>(Wl);

    // ---- layer 1 attention ----
    proj_kernel<<<128, 256>>>(W1, q1, k1, p_pq, p_pk);
    sqsk_kernel<<<SQB, 128>>>(x);
    agg_fused<<<AGB, 256>>>(b1, p_h1);

    // ---- layer 2 ----
    prep_a_kernel<<<MBLK, 128>>>(p_h1, NN);
    prep_b_kernel<<<RR, 128>>>(W2);
    gemm_mma<<<dim3(MBLK, RR), 256, SMEM_BYTES>>>(p_xw, NN, nullptr);
    proj_kernel<<<128, 256>>>(W2, q2, k2, p_pq, p_pk);
    sqsk_kernel<<<SQB, 128>>>(p_h1);
    agg_fused<<<AGB, 256>>>(b2, p_h2);

    // ---- final linear straight into d_out ----
    prep_a_kernel<<<MBLK, 128>>>(p_h2, NN);
    prep_b_kernel<<<1, 128>>>(p_wlt);
    gemm_mma<<<dim3(MBLK, 1), 256, SMEM_BYTES>>>((float*)d_out, NN, bl);
}